// round 3
// baseline (speedup 1.0000x reference)
#include <cuda_runtime.h>
#include <cuda_bf16.h>

#define NN    8000
#define NFEAT 512
#define NHID  128
#define NCLS  64
#define MAXNB 96

// ---- scratch (static device globals; no runtime allocation) ----
__device__ float g_h[NN * NHID];        // h = relu(x@W0+b0) == h0 == li_0
__device__ float g_Pseudo[NN * NCLS];
__device__ float g_yhat[NN * NCLS];
__device__ float g_liA[NN * NHID];
__device__ float g_liB[NN * NHID];
__device__ int   g_cols[NN * MAXNB];
__device__ float g_vals[NN * MAXNB];
__device__ int   g_nnz[NN];

// ---------------------------------------------------------------
// GEMM1: h = relu(x @ W0 + b0).  [8000,512]@[512,128]
// 64x64x16 tiles, 4x4 microtiles, 256 threads. grid (2,125).
// ---------------------------------------------------------------
__global__ void k_gemm1(const float* __restrict__ x,
                        const float* __restrict__ W0,
                        const float* __restrict__ b0) {
    __shared__ float As[16][64];
    __shared__ float Bs[16][64];
    const int tid  = threadIdx.x;
    const int bCol = blockIdx.x;     // 0..1  (N)
    const int bRow = blockIdx.y;     // 0..124 (M) ; 125*64 == 8000 exactly
    const int tRow = tid >> 4;       // 0..15
    const int tCol = tid & 15;       // 0..15

    const int aRow = tid >> 2;           // 0..63
    const int aK   = (tid & 3) * 4;      // 0,4,8,12
    const int bK   = tid >> 4;           // 0..15
    const int bN   = (tid & 15) * 4;     // 0..60

    const float* Ag = x + (size_t)(bRow * 64 + aRow) * NFEAT;
    const float* Bg = W0 + bCol * 64;

    float acc[4][4];
#pragma unroll
    for (int i = 0; i < 4; i++)
#pragma unroll
        for (int j = 0; j < 4; j++) acc[i][j] = 0.f;

    for (int kt = 0; kt < NFEAT; kt += 16) {
        float4 av = *(const float4*)(Ag + kt + aK);
        As[aK + 0][aRow] = av.x;
        As[aK + 1][aRow] = av.y;
        As[aK + 2][aRow] = av.z;
        As[aK + 3][aRow] = av.w;
        float4 bv = *(const float4*)(Bg + (size_t)(kt + bK) * NHID + bN);
        *(float4*)&Bs[bK][bN] = bv;
        __syncthreads();
#pragma unroll
        for (int k = 0; k < 16; k++) {
            float rm[4], rn[4];
#pragma unroll
            for (int i = 0; i < 4; i++) rm[i] = As[k][tRow * 4 + i];
#pragma unroll
            for (int j = 0; j < 4; j++) rn[j] = Bs[k][tCol * 4 + j];
#pragma unroll
            for (int i = 0; i < 4; i++)
#pragma unroll
                for (int j = 0; j < 4; j++) acc[i][j] += rm[i] * rn[j];
        }
        __syncthreads();
    }
#pragma unroll
    for (int i = 0; i < 4; i++) {
        int row = bRow * 64 + tRow * 4 + i;
#pragma unroll
        for (int j = 0; j < 4; j++) {
            int col = bCol * 64 + tCol * 4 + j;
            float v = acc[i][j] + b0[col];
            g_h[row * NHID + col] = v > 0.f ? v : 0.f;
        }
    }
}

// ---------------------------------------------------------------
// Pseudo = h @ W1 + b1.   [8000,128]@[128,64]
// 8 warps/block, warp-per-row, W1 staged in smem. grid 1000.
// ---------------------------------------------------------------
__global__ void k_pseudo(const float* __restrict__ W1,
                         const float* __restrict__ b1) {
    __shared__ float Ws[NHID * NCLS];
    __shared__ float bs[NCLS];
    __shared__ float rowbuf[8][NHID];
    const int tid = threadIdx.x;
    for (int i = tid; i < NHID * NCLS; i += 256) Ws[i] = W1[i];
    if (tid < NCLS) bs[tid] = b1[tid];
    __syncthreads();

    const int warp = tid >> 5, lane = tid & 31;
    const int row  = blockIdx.x * 8 + warp;
    float4 v = *(const float4*)(g_h + (size_t)row * NHID + lane * 4);
    *(float4*)&rowbuf[warp][lane * 4] = v;
    __syncwarp();

    const int c0 = lane * 2, c1 = c0 + 1;
    float a0 = bs[c0], a1 = bs[c1];
#pragma unroll 8
    for (int k = 0; k < NHID; k++) {
        float hk = rowbuf[warp][k];
        a0 += hk * Ws[k * NCLS + c0];
        a1 += hk * Ws[k * NCLS + c1];
    }
    g_Pseudo[row * NCLS + c0] = a0;
    g_Pseudo[row * NCLS + c1] = a1;
}

// Pseudo[idx[t]] += 0.1*y_label[idx[t]]  (duplicates accumulate)
__global__ void k_scatter(const int* __restrict__ idx,
                          const float* __restrict__ ylab) {
    int r = idx[blockIdx.x];
    int c = threadIdx.x;
    float v = 0.1f * ylab[r * NCLS + c];
    if (v != 0.f) atomicAdd(&g_Pseudo[r * NCLS + c], v);
}

// y_hat = softmax(Pseudo); also emit Pseudo to the output buffer.
__global__ void k_softmax(float* __restrict__ outPseudo) {
    const int row  = blockIdx.x * 8 + (threadIdx.x >> 5);
    const int lane = threadIdx.x & 31;
    float2 p = *(const float2*)(g_Pseudo + row * NCLS + lane * 2);
    *(float2*)(outPseudo + row * NCLS + lane * 2) = p;
    float m = fmaxf(p.x, p.y);
#pragma unroll
    for (int o = 16; o; o >>= 1) m = fmaxf(m, __shfl_xor_sync(~0u, m, o));
    float e0 = expf(p.x - m), e1 = expf(p.y - m);
    float s = e0 + e1;
#pragma unroll
    for (int o = 16; o; o >>= 1) s += __shfl_xor_sync(~0u, s, o);
    float inv = 1.f / s;
    float2 y; y.x = e0 * inv; y.y = e1 * inv;
    *(float2*)(g_yhat + row * NCLS + lane * 2) = y;
}

// Extract adjacency structure (ELL, cap MAXNB/row). Warp-per-row,
// ballot/popc compaction, fully coalesced 256MB read.
__global__ void k_csr(const float* __restrict__ adj) {
    const int row  = blockIdx.x * 8 + (threadIdx.x >> 5);
    const int lane = threadIdx.x & 31;
    const float* arow = adj + (size_t)row * NN;
    int count = 0;
    for (int j0 = 0; j0 < NN; j0 += 32) {
        float v = arow[j0 + lane];
        unsigned m = __ballot_sync(~0u, v != 0.f);
        if (v != 0.f) {
            int pos = count + __popc(m & ((1u << lane) - 1u));
            if (pos < MAXNB) g_cols[row * MAXNB + pos] = j0 + lane;
        }
        count += __popc(m);
    }
    if (lane == 0) g_nnz[row] = count < MAXNB ? count : MAXNB;
}

// vals[i,k] = dot(yhat[i], yhat[col_k]) / max(rowsum, eps)
// (adj nonzeros are exactly 1.0, so a == mask at nonzeros)
__global__ void k_mask() {
    const int row  = blockIdx.x * 8 + (threadIdx.x >> 5);
    const int lane = threadIdx.x & 31;
    float2 yi = *(const float2*)(g_yhat + row * NCLS + lane * 2);
    const int nnz = g_nnz[row];
    const int off = row * MAXNB;
    float rsum = 0.f;
    for (int k = 0; k < nnz; k++) {
        int c = g_cols[off + k];
        float2 yj = *(const float2*)(g_yhat + c * NCLS + lane * 2);
        float d = yi.x * yj.x + yi.y * yj.y;
#pragma unroll
        for (int o = 16; o; o >>= 1) d += __shfl_xor_sync(~0u, d, o);
        if (lane == 0) g_vals[off + k] = d;
        rsum += d;   // identical on every lane after xor-reduce
    }
    __syncwarp();
    float inv = 1.f / fmaxf(rsum, 1e-12f);
    for (int k = lane; k < nnz; k += 32) g_vals[off + k] *= inv;
}

// li_new[i] = L2normalize(0.9 * sum_k w_k * li[col_k] + 0.1 * h0[i])
__global__ void k_spmm(int layer) {
    const float* src = (layer == 0) ? g_h   : g_liA;
    float*       dst = (layer == 0) ? g_liA : g_liB;
    const int row  = blockIdx.x * 8 + (threadIdx.x >> 5);
    const int lane = threadIdx.x & 31;
    const int nnz = g_nnz[row];
    const int off = row * MAXNB;
    float4 acc = make_float4(0.f, 0.f, 0.f, 0.f);
    for (int k = 0; k < nnz; k++) {
        int   c = g_cols[off + k];
        float w = g_vals[off + k];
        float4 v = *(const float4*)(src + (size_t)c * NHID + lane * 4);
        acc.x += w * v.x; acc.y += w * v.y; acc.z += w * v.z; acc.w += w * v.w;
    }
    float4 h0 = *(const float4*)(g_h + (size_t)row * NHID + lane * 4);
    float4 r;
    r.x = 0.9f * acc.x + 0.1f * h0.x;
    r.y = 0.9f * acc.y + 0.1f * h0.y;
    r.z = 0.9f * acc.z + 0.1f * h0.z;
    r.w = 0.9f * acc.w + 0.1f * h0.w;
    float ss = r.x * r.x + r.y * r.y + r.z * r.z + r.w * r.w;
#pragma unroll
    for (int o = 16; o; o >>= 1) ss += __shfl_xor_sync(~0u, ss, o);
    float inv = 1.f / fmaxf(sqrtf(ss), 1e-12f);
    r.x *= inv; r.y *= inv; r.z *= inv; r.w *= inv;
    *(float4*)(dst + (size_t)row * NHID + lane * 4) = r;
}

// out = log_softmax(liB @ W2 + b2)
__global__ void k_out(const float* __restrict__ W2,
                      const float* __restrict__ b2,
                      float* __restrict__ out) {
    __shared__ float Ws[NHID * NCLS];
    __shared__ float bs[NCLS];
    __shared__ float rowbuf[8][NHID];
    const int tid = threadIdx.x;
    for (int i = tid; i < NHID * NCLS; i += 256) Ws[i] = W2[i];
    if (tid < NCLS) bs[tid] = b2[tid];
    __syncthreads();

    const int warp = tid >> 5, lane = tid & 31;
    const int row  = blockIdx.x * 8 + warp;
    float4 v = *(const float4*)(g_liB + (size_t)row * NHID + lane * 4);
    *(float4*)&rowbuf[warp][lane * 4] = v;
    __syncwarp();

    const int c0 = lane * 2, c1 = c0 + 1;
    float a0 = bs[c0], a1 = bs[c1];
#pragma unroll 8
    for (int k = 0; k < NHID; k++) {
        float hk = rowbuf[warp][k];
        a0 += hk * Ws[k * NCLS + c0];
        a1 += hk * Ws[k * NCLS + c1];
    }
    float m = fmaxf(a0, a1);
#pragma unroll
    for (int o = 16; o; o >>= 1) m = fmaxf(m, __shfl_xor_sync(~0u, m, o));
    float e0 = expf(a0 - m), e1 = expf(a1 - m);
    float s = e0 + e1;
#pragma unroll
    for (int o = 16; o; o >>= 1) s += __shfl_xor_sync(~0u, s, o);
    float ls = logf(s);
    out[row * NCLS + c0] = a0 - m - ls;
    out[row * NCLS + c1] = a1 - m - ls;
}

extern "C" void kernel_launch(void* const* d_in, const int* in_sizes, int n_in,
                              void* d_out, int out_size) {
    const float* x    = (const float*)d_in[0];   // [8000,512]
    const float* adj  = (const float*)d_in[1];   // [8000,8000]
    const float* ylab = (const float*)d_in[2];   // [8000,64]
    const int*   idx  = (const int*)  d_in[3];   // [500]
    const float* W0   = (const float*)d_in[4];
    const float* b0   = (const float*)d_in[5];
    const float* W1   = (const float*)d_in[6];
    const float* b1   = (const float*)d_in[7];
    const float* W2   = (const float*)d_in[8];
    const float* b2   = (const float*)d_in[9];
    float* out = (float*)d_out;                  // [log_softmax | Pseudo]

    k_gemm1<<<dim3(2, 125), 256>>>(x, W0, b0);
    k_csr<<<1000, 256>>>(adj);                   // independent of GEMMs
    k_pseudo<<<1000, 256>>>(W1, b1);
    k_scatter<<<500, 64>>>(idx, ylab);
    k_softmax<<<1000, 256>>>(out + NN * NCLS);
    k_mask<<<1000, 256>>>();
    k_spmm<<<1000, 256>>>(0);
    k_spmm<<<1000, 256>>>(1);
    k_out<<<1000, 256>>>(W2, b2, out);
}

// round 4
// speedup vs baseline: 1.1156x; 1.1156x over previous
#include <cuda_runtime.h>
#include <cuda_bf16.h>

#define NN    8000
#define NFEAT 512
#define NHID  128
#define NCLS  64
#define MAXNB 96
#define NIDX  500

// ---- scratch (static device globals; no runtime allocation) ----
__device__ float g_h[NN * NHID];        // h = relu(x@W0+b0) == h0
__device__ float g_yhat[NN * NCLS];
__device__ float g_liA[NN * NHID];
__device__ int   g_cols[NN * MAXNB];
__device__ float g_vals[NN * MAXNB];
__device__ int   g_nnz[NN];

// ===============================================================
// K1: heterogeneous front end.
//   blocks [0,1000):     adjacency ELL extraction (DRAM-bound)
//   blocks [1000,1250):  GEMM1 h = relu(x@W0+b0)  (FFMA-bound)
// Independent work; one launch so the two bottlenecks overlap.
// ===============================================================
__global__ void __launch_bounds__(256) k_front(const float* __restrict__ adj,
                                               const float* __restrict__ x,
                                               const float* __restrict__ W0,
                                               const float* __restrict__ b0) {
    __shared__ float As[16][64];
    __shared__ float Bs[16][64];

    if (blockIdx.x < 1000) {
        // ---------- adjacency scan: warp per row, float4 loads ----------
        const int row  = blockIdx.x * 8 + (threadIdx.x >> 5);
        const int lane = threadIdx.x & 31;
        const float* arow = adj + (size_t)row * NN;
        const float4* arow4 = (const float4*)arow;
        int count = 0;
        const unsigned below = (1u << lane) - 1u;
        // 62 groups of 128 floats = 7936
        for (int g = 0; g < 62; g++) {
            float4 v = arow4[g * 32 + lane];
            int base = g * 128 + lane * 4;
            float e[4] = {v.x, v.y, v.z, v.w};
#pragma unroll
            for (int c = 0; c < 4; c++) {
                unsigned m = __ballot_sync(~0u, e[c] != 0.f);
                if (e[c] != 0.f) {
                    int pos = count + __popc(m & below);
                    if (pos < MAXNB) g_cols[row * MAXNB + pos] = base + c;
                }
                count += __popc(m);
            }
        }
        // tail: 64 floats at 7936, float2 per lane
        {
            float2 t = ((const float2*)(arow + 7936))[lane];
            float e[2] = {t.x, t.y};
#pragma unroll
            for (int c = 0; c < 2; c++) {
                unsigned m = __ballot_sync(~0u, e[c] != 0.f);
                if (e[c] != 0.f) {
                    int pos = count + __popc(m & below);
                    if (pos < MAXNB) g_cols[row * MAXNB + pos] = 7936 + lane * 2 + c;
                }
                count += __popc(m);
            }
        }
        if (lane == 0) g_nnz[row] = count < MAXNB ? count : MAXNB;
    } else {
        // ---------- GEMM1: 64x64x16 tiles, 4x4 microtiles ----------
        const int bid  = blockIdx.x - 1000;       // 0..249
        const int bCol = bid / 125;               // 0..1
        const int bRow = bid % 125;               // 0..124
        const int tid  = threadIdx.x;
        const int tRow = tid >> 4;
        const int tCol = tid & 15;
        const int aRow = tid >> 2;
        const int aK   = (tid & 3) * 4;
        const int bK   = tid >> 4;
        const int bN   = (tid & 15) * 4;

        const float* Ag = x + (size_t)(bRow * 64 + aRow) * NFEAT;
        const float* Bg = W0 + bCol * 64;

        float acc[4][4];
#pragma unroll
        for (int i = 0; i < 4; i++)
#pragma unroll
            for (int j = 0; j < 4; j++) acc[i][j] = 0.f;

        for (int kt = 0; kt < NFEAT; kt += 16) {
            float4 av = *(const float4*)(Ag + kt + aK);
            As[aK + 0][aRow] = av.x;
            As[aK + 1][aRow] = av.y;
            As[aK + 2][aRow] = av.z;
            As[aK + 3][aRow] = av.w;
            float4 bv = *(const float4*)(Bg + (size_t)(kt + bK) * NHID + bN);
            *(float4*)&Bs[bK][bN] = bv;
            __syncthreads();
#pragma unroll
            for (int k = 0; k < 16; k++) {
                float rm[4], rn[4];
#pragma unroll
                for (int i = 0; i < 4; i++) rm[i] = As[k][tRow * 4 + i];
#pragma unroll
                for (int j = 0; j < 4; j++) rn[j] = Bs[k][tCol * 4 + j];
#pragma unroll
                for (int i = 0; i < 4; i++)
#pragma unroll
                    for (int j = 0; j < 4; j++) acc[i][j] += rm[i] * rn[j];
            }
            __syncthreads();
        }
#pragma unroll
        for (int i = 0; i < 4; i++) {
            int row = bRow * 64 + tRow * 4 + i;
#pragma unroll
            for (int j = 0; j < 4; j++) {
                int col = bCol * 64 + tCol * 4 + j;
                float v = acc[i][j] + b0[col];
                g_h[row * NHID + col] = v > 0.f ? v : 0.f;
            }
        }
    }
}

// ===============================================================
// K2: Pseudo = h@W1+b1 + 0.1*cnt(row)*y_label[row];
//     emit Pseudo; y_hat = softmax(Pseudo).
// idx_train is sorted -> cnt(row) via binary search in smem.
// ===============================================================
__global__ void __launch_bounds__(256) k_pseudo_fused(const float* __restrict__ W1,
                                                      const float* __restrict__ b1,
                                                      const int*   __restrict__ idx,
                                                      const float* __restrict__ ylab,
                                                      float* __restrict__ outPseudo) {
    __shared__ float Ws[NHID * NCLS];
    __shared__ float bs[NCLS];
    __shared__ float rowbuf[8][NHID];
    __shared__ int   s_idx[NIDX];
    const int tid = threadIdx.x;
    for (int i = tid; i < NHID * NCLS; i += 256) Ws[i] = W1[i];
    if (tid < NCLS) bs[tid] = b1[tid];
    for (int i = tid; i < NIDX; i += 256) s_idx[i] = idx[i];
    __syncthreads();

    const int warp = tid >> 5, lane = tid & 31;
    const int row  = blockIdx.x * 8 + warp;
    float4 v = *(const float4*)(g_h + (size_t)row * NHID + lane * 4);
    *(float4*)&rowbuf[warp][lane * 4] = v;
    __syncwarp();

    // count of row in sorted idx
    int lo = 0, hi = NIDX;
    while (lo < hi) { int mid = (lo + hi) >> 1; if (s_idx[mid] < row) lo = mid + 1; else hi = mid; }
    int lb = lo; hi = NIDX;
    while (lo < hi) { int mid = (lo + hi) >> 1; if (s_idx[mid] <= row) lo = mid + 1; else hi = mid; }
    const float cf = 0.1f * (float)(lo - lb);

    const int c0 = lane * 2, c1 = c0 + 1;
    float a0 = bs[c0], a1 = bs[c1];
#pragma unroll 8
    for (int k = 0; k < NHID; k++) {
        float hk = rowbuf[warp][k];
        a0 += hk * Ws[k * NCLS + c0];
        a1 += hk * Ws[k * NCLS + c1];
    }
    if (cf != 0.f) {
        a0 += cf * ylab[row * NCLS + c0];
        a1 += cf * ylab[row * NCLS + c1];
    }
    float2 p; p.x = a0; p.y = a1;
    *(float2*)(outPseudo + row * NCLS + c0) = p;

    float m = fmaxf(a0, a1);
#pragma unroll
    for (int o = 16; o; o >>= 1) m = fmaxf(m, __shfl_xor_sync(~0u, m, o));
    float e0 = expf(a0 - m), e1 = expf(a1 - m);
    float s = e0 + e1;
#pragma unroll
    for (int o = 16; o; o >>= 1) s += __shfl_xor_sync(~0u, s, o);
    float inv = 1.f / s;
    float2 y; y.x = e0 * inv; y.y = e1 * inv;
    *(float2*)(g_yhat + row * NCLS + c0) = y;
}

// ===============================================================
// K3: mask weights + SpMM layer 0 + residual + L2 norm -> liA.
//     Also persists normalized vals for layer 1.
// ===============================================================
__global__ void __launch_bounds__(256) k_mask_spmm0() {
    __shared__ float vals_s[8][MAXNB];
    __shared__ int   cols_s[8][MAXNB];
    const int warp = threadIdx.x >> 5, lane = threadIdx.x & 31;
    const int row  = blockIdx.x * 8 + warp;
    const int nnz  = g_nnz[row];
    const int off  = row * MAXNB;
    for (int k = lane; k < nnz; k += 32) cols_s[warp][k] = g_cols[off + k];
    __syncwarp();

    float2 yi = *(const float2*)(g_yhat + row * NCLS + lane * 2);
    float rsum = 0.f;
    for (int k = 0; k < nnz; k++) {
        int c = cols_s[warp][k];
        float2 yj = *(const float2*)(g_yhat + c * NCLS + lane * 2);
        float d = yi.x * yj.x + yi.y * yj.y;
#pragma unroll
        for (int o = 16; o; o >>= 1) d += __shfl_xor_sync(~0u, d, o);
        if (lane == 0) vals_s[warp][k] = d;
        rsum += d;
    }
    __syncwarp();
    const float inv = 1.f / fmaxf(rsum, 1e-12f);
    for (int k = lane; k < nnz; k += 32) g_vals[off + k] = vals_s[warp][k] * inv;

    float4 acc = make_float4(0.f, 0.f, 0.f, 0.f);
    for (int k = 0; k < nnz; k++) {
        int   c = cols_s[warp][k];
        float w = vals_s[warp][k] * inv;
        float4 v = *(const float4*)(g_h + (size_t)c * NHID + lane * 4);
        acc.x += w * v.x; acc.y += w * v.y; acc.z += w * v.z; acc.w += w * v.w;
    }
    float4 h0 = *(const float4*)(g_h + (size_t)row * NHID + lane * 4);
    float4 r;
    r.x = 0.9f * acc.x + 0.1f * h0.x;
    r.y = 0.9f * acc.y + 0.1f * h0.y;
    r.z = 0.9f * acc.z + 0.1f * h0.z;
    r.w = 0.9f * acc.w + 0.1f * h0.w;
    float ss = r.x * r.x + r.y * r.y + r.z * r.z + r.w * r.w;
#pragma unroll
    for (int o = 16; o; o >>= 1) ss += __shfl_xor_sync(~0u, ss, o);
    float ninv = 1.f / fmaxf(sqrtf(ss), 1e-12f);
    r.x *= ninv; r.y *= ninv; r.z *= ninv; r.w *= ninv;
    *(float4*)(g_liA + (size_t)row * NHID + lane * 4) = r;
}

// ===============================================================
// K4: SpMM layer 1 + residual + L2 norm, then directly
//     out = log_softmax(liB_row @ W2 + b2).
// ===============================================================
__global__ void __launch_bounds__(256) k_spmm1_out(const float* __restrict__ W2,
                                                   const float* __restrict__ b2,
                                                   float* __restrict__ out) {
    __shared__ float Ws[NHID * NCLS];
    __shared__ float bs[NCLS];
    __shared__ float rowbuf[8][NHID];
    const int tid = threadIdx.x;
    for (int i = tid; i < NHID * NCLS; i += 256) Ws[i] = W2[i];
    if (tid < NCLS) bs[tid] = b2[tid];
    __syncthreads();

    const int warp = tid >> 5, lane = tid & 31;
    const int row  = blockIdx.x * 8 + warp;
    const int nnz  = g_nnz[row];
    const int off  = row * MAXNB;

    float4 acc = make_float4(0.f, 0.f, 0.f, 0.f);
    for (int k = 0; k < nnz; k++) {
        int   c = g_cols[off + k];
        float w = g_vals[off + k];
        float4 v = *(const float4*)(g_liA + (size_t)c * NHID + lane * 4);
        acc.x += w * v.x; acc.y += w * v.y; acc.z += w * v.z; acc.w += w * v.w;
    }
    float4 h0 = *(const float4*)(g_h + (size_t)row * NHID + lane * 4);
    float4 r;
    r.x = 0.9f * acc.x + 0.1f * h0.x;
    r.y = 0.9f * acc.y + 0.1f * h0.y;
    r.z = 0.9f * acc.z + 0.1f * h0.z;
    r.w = 0.9f * acc.w + 0.1f * h0.w;
    float ss = r.x * r.x + r.y * r.y + r.z * r.z + r.w * r.w;
#pragma unroll
    for (int o = 16; o; o >>= 1) ss += __shfl_xor_sync(~0u, ss, o);
    float ninv = 1.f / fmaxf(sqrtf(ss), 1e-12f);
    r.x *= ninv; r.y *= ninv; r.z *= ninv; r.w *= ninv;
    *(float4*)&rowbuf[warp][lane * 4] = r;
    __syncwarp();

    const int c0 = lane * 2, c1 = c0 + 1;
    float a0 = bs[c0], a1 = bs[c1];
#pragma unroll 8
    for (int k = 0; k < NHID; k++) {
        float hk = rowbuf[warp][k];
        a0 += hk * Ws[k * NCLS + c0];
        a1 += hk * Ws[k * NCLS + c1];
    }
    float m = fmaxf(a0, a1);
#pragma unroll
    for (int o = 16; o; o >>= 1) m = fmaxf(m, __shfl_xor_sync(~0u, m, o));
    float e0 = expf(a0 - m), e1 = expf(a1 - m);
    float s = e0 + e1;
#pragma unroll
    for (int o = 16; o; o >>= 1) s += __shfl_xor_sync(~0u, s, o);
    float ls = logf(s);
    out[row * NCLS + c0] = a0 - m - ls;
    out[row * NCLS + c1] = a1 - m - ls;
}

extern "C" void kernel_launch(void* const* d_in, const int* in_sizes, int n_in,
                              void* d_out, int out_size) {
    const float* x    = (const float*)d_in[0];   // [8000,512]
    const float* adj  = (const float*)d_in[1];   // [8000,8000]
    const float* ylab = (const float*)d_in[2];   // [8000,64]
    const int*   idx  = (const int*)  d_in[3];   // [500] sorted
    const float* W0   = (const float*)d_in[4];
    const float* b0   = (const float*)d_in[5];
    const float* W1   = (const float*)d_in[6];
    const float* b1   = (const float*)d_in[7];
    const float* W2   = (const float*)d_in[8];
    const float* b2   = (const float*)d_in[9];
    float* out = (float*)d_out;                  // [log_softmax | Pseudo]

    k_front<<<1250, 256>>>(adj, x, W0, b0);
    k_pseudo_fused<<<1000, 256>>>(W1, b1, idx, ylab, out + NN * NCLS);
    k_mask_spmm0<<<1000, 256>>>();
    k_spmm1_out<<<1000, 256>>>(W2, b2, out);
}